// round 15
// baseline (speedup 1.0000x reference)
#include <cuda_runtime.h>
#include <cuda_bf16.h>
#include <math.h>
#include <stdint.h>

#define Bb 4
#define Cc 128
#define Kk 64
#define Hh 256
#define Ww 256
#define HW (Hh*Ww)
#define NT 256          // B * P*P tiles
#define MID_SMEM_FLOATS 51072
#define MID_SMEM (MID_SMEM_FLOATS*4)
#define LDB 72          // bf16 elements per smem row (64 data + 8 pad)
#define GRAM2_SMEM 73728
#define OUT4_SMEM 215296

typedef unsigned short ush;

// ---- packed fp32x2 helpers (FFMA2) ----
typedef unsigned long long u64t;
__device__ __forceinline__ u64t f2pack(float lo, float hi){
    u64t r; asm("mov.b64 %0, {%1,%2};" : "=l"(r) : "f"(lo), "f"(hi)); return r;
}
__device__ __forceinline__ u64t f2splat(float v){ return f2pack(v, v); }
__device__ __forceinline__ void f2unpack(u64t v, float& lo, float& hi){
    asm("mov.b64 {%0,%1}, %2;" : "=f"(lo), "=f"(hi) : "l"(v));
}
__device__ __forceinline__ void f2fma(u64t& d, u64t a, u64t b){
    asm("fma.rn.f32x2 %0, %1, %2, %3;" : "=l"(d) : "l"(a), "l"(b), "l"(d));
}

// ---- mma.sync helpers (arch-neutral tensor path) ----
__device__ __forceinline__ uint32_t s2u(const void* p){
    uint32_t a;
    asm("{ .reg .u64 t; cvta.to.shared.u64 t, %1; cvt.u32.u64 %0, t; }" : "=r"(a) : "l"(p));
    return a;
}
__device__ __forceinline__ void ldm4(uint32_t* d, uint32_t addr){
    asm volatile("ldmatrix.sync.aligned.m8n8.x4.shared.b16 {%0,%1,%2,%3}, [%4];"
        : "=r"(d[0]), "=r"(d[1]), "=r"(d[2]), "=r"(d[3]) : "r"(addr));
}
__device__ __forceinline__ void ldm4t(uint32_t* d, uint32_t addr){
    asm volatile("ldmatrix.sync.aligned.m8n8.x4.trans.shared.b16 {%0,%1,%2,%3}, [%4];"
        : "=r"(d[0]), "=r"(d[1]), "=r"(d[2]), "=r"(d[3]) : "r"(addr));
}
__device__ __forceinline__ void mma16816(float* c, const uint32_t* a, const uint32_t* b){
    asm volatile("mma.sync.aligned.m16n8k16.row.col.f32.bf16.bf16.f32 "
        "{%0,%1,%2,%3}, {%4,%5,%6,%7}, {%8,%9}, {%0,%1,%2,%3};"
        : "+f"(c[0]), "+f"(c[1]), "+f"(c[2]), "+f"(c[3])
        : "r"(a[0]), "r"(a[1]), "r"(a[2]), "r"(a[3]), "r"(b[0]), "r"(b[1]));
}
__device__ __forceinline__ uint32_t bfp(__nv_bfloat16 a, __nv_bfloat16 b){
    return ((uint32_t)__bfloat16_as_ushort(b) << 16) | (uint32_t)__bfloat16_as_ushort(a);
}
__device__ __forceinline__ uint32_t bfp2(float a, float b){
    return bfp(__float2bfloat16(a), __float2bfloat16(b));
}

// Scratch (allocation-free rule: __device__ globals)
__device__ float dG[2*NT*Cc*Cc];   // per (stream,tile) Gram 128x128
__device__ float dS[2*NT*Cc];      // per (stream,tile) row sums
__device__ ush   dAh[2*NT*Cc*Kk];  // A hi bf16, layout [s][t][o=128][k=64]
__device__ ush   dAl[2*NT*Cc*Kk];  // A lo bf16

// ---------------------------------------------------------------------------
// Kernel A (HMMA, R10/R13 version): G = X X^T = HH + Q + Q^T.
// ---------------------------------------------------------------------------
__global__ __launch_bounds__(256) void gram_kernel(const float* __restrict__ x1,
                                                   const float* __restrict__ x2)
{
    extern __shared__ char gsm[];
    uint32_t gb = s2u(gsm);

    int t = blockIdx.x, s = blockIdx.y;
    const float* x = s ? x2 : x1;
    int b = t >> 6, q = t & 63;
    int pi = q >> 3, pj = q & 7;
    long base0 = (long)b*Cc*HW + (long)(pi*32)*Ww + pj*32;

    int tid = threadIdx.x, wid = tid >> 5, lane = tid & 31;
    int c0 = tid >> 1, half = tid & 1;
    const float* rowbase = x + base0 + (long)c0*HW + (long)half*Ww;

    int wm = wid & 3, wn = wid >> 2;
    int m0 = wm*32, n0 = wn*64;

    float acc_hh[2][8][4], acc_q[2][8][4];
    #pragma unroll
    for (int a = 0; a < 2; a++)
        #pragma unroll
        for (int nt = 0; nt < 8; nt++)
            #pragma unroll
            for (int e = 0; e < 4; e++) { acc_hh[a][nt][e] = 0.f; acc_q[a][nt][e] = 0.f; }

    float ps = 0.f;
    float4 pref[8];
    {
        const float4* src = (const float4*)rowbase;
        #pragma unroll
        for (int j = 0; j < 8; j++) pref[j] = src[j];
    }

    uint32_t aRow = (uint32_t)(lane & 15);
    uint32_t aKof = (uint32_t)((lane >> 4) << 3);
    uint32_t bRow = (uint32_t)((lane & 7) + ((lane >> 4) << 3));
    uint32_t bKof = (uint32_t)(((lane >> 3) & 1) << 3);

    uint32_t wo = ((uint32_t)c0*LDB + (uint32_t)half*32u)*2u;

    #pragma unroll
    for (int j = 0; j < 8; j++) {
        float4 v = pref[j];
        ps += (v.x + v.y) + (v.z + v.w);
        __nv_bfloat16 hx = __float2bfloat16(v.x), hy = __float2bfloat16(v.y),
                      hz = __float2bfloat16(v.z), hw = __float2bfloat16(v.w);
        uint32_t off = wo + 8u*j;
        *(uint2*)(gsm + off) = make_uint2(bfp(hx, hy), bfp(hz, hw));
        *(uint2*)(gsm + 18432 + off) = make_uint2(
            bfp2(v.x - __bfloat162float(hx), v.y - __bfloat162float(hy)),
            bfp2(v.z - __bfloat162float(hz), v.w - __bfloat162float(hw)));
    }
    {
        const float4* src = (const float4*)(rowbase + (long)2*Ww);
        #pragma unroll
        for (int j = 0; j < 8; j++) pref[j] = src[j];
    }
    __syncthreads();

    for (int ch = 0; ch < 16; ch++) {
        uint32_t hiB = gb + (uint32_t)(ch & 1)*36864u;
        uint32_t loB = hiB + 18432u;

        #pragma unroll
        for (int ks = 0; ks < 4; ks++) {
            uint32_t k0 = (uint32_t)(ks*16);
            uint32_t ahi[2][4], bhi[8][2], blo[8][2];
            #pragma unroll
            for (int a = 0; a < 2; a++) {
                uint32_t eo = ((uint32_t)(m0 + a*16) + aRow)*LDB + k0 + aKof;
                ldm4(ahi[a], hiB + eo*2u);
            }
            #pragma unroll
            for (int p = 0; p < 4; p++) {
                uint32_t eo = ((uint32_t)(n0 + p*16) + bRow)*LDB + k0 + bKof;
                uint32_t r[4];
                ldm4(r, hiB + eo*2u);
                bhi[2*p][0] = r[0]; bhi[2*p][1] = r[1];
                bhi[2*p+1][0] = r[2]; bhi[2*p+1][1] = r[3];
                ldm4(r, loB + eo*2u);
                blo[2*p][0] = r[0]; blo[2*p][1] = r[1];
                blo[2*p+1][0] = r[2]; blo[2*p+1][1] = r[3];
            }
            #pragma unroll
            for (int a = 0; a < 2; a++)
                #pragma unroll
                for (int nt = 0; nt < 8; nt++) {
                    mma16816(acc_hh[a][nt], ahi[a], bhi[nt]);
                    mma16816(acc_q[a][nt],  ahi[a], blo[nt]);
                }
        }

        if (ch < 15) {
            char* dsth = gsm + ((ch + 1) & 1)*36864;
            #pragma unroll
            for (int j = 0; j < 8; j++) {
                float4 v = pref[j];
                ps += (v.x + v.y) + (v.z + v.w);
                __nv_bfloat16 hx = __float2bfloat16(v.x), hy = __float2bfloat16(v.y),
                              hz = __float2bfloat16(v.z), hw = __float2bfloat16(v.w);
                uint32_t off = wo + 8u*j;
                *(uint2*)(dsth + off) = make_uint2(bfp(hx, hy), bfp(hz, hw));
                *(uint2*)(dsth + 18432 + off) = make_uint2(
                    bfp2(v.x - __bfloat162float(hx), v.y - __bfloat162float(hy)),
                    bfp2(v.z - __bfloat162float(hz), v.w - __bfloat162float(hw)));
            }
            if (ch < 14) {
                const float4* src = (const float4*)(rowbase + (long)((ch + 2)*2)*Ww);
                #pragma unroll
                for (int j = 0; j < 8; j++) pref[j] = src[j];
            }
        }
        __syncthreads();
    }

    {
        float* Qs = (float*)gsm;
        int grp = lane >> 2, tix = lane & 3;
        #pragma unroll
        for (int a = 0; a < 2; a++)
            #pragma unroll
            for (int nt = 0; nt < 8; nt++) {
                int r0 = m0 + a*16 + grp, cc = n0 + nt*8 + tix*2;
                Qs[r0*132 + cc]       = acc_q[a][nt][0];
                Qs[r0*132 + cc + 1]   = acc_q[a][nt][1];
                Qs[(r0+8)*132 + cc]   = acc_q[a][nt][2];
                Qs[(r0+8)*132 + cc+1] = acc_q[a][nt][3];
            }
        __syncthreads();
        float* Gout = dG + (long)(s*NT + t)*(Cc*Cc);
        #pragma unroll
        for (int a = 0; a < 2; a++)
            #pragma unroll
            for (int nt = 0; nt < 8; nt++) {
                int r0 = m0 + a*16 + grp, cc = n0 + nt*8 + tix*2;
                float2 v0, v1;
                v0.x = acc_hh[a][nt][0] + acc_q[a][nt][0] + Qs[cc*132 + r0];
                v0.y = acc_hh[a][nt][1] + acc_q[a][nt][1] + Qs[(cc+1)*132 + r0];
                v1.x = acc_hh[a][nt][2] + acc_q[a][nt][2] + Qs[cc*132 + r0 + 8];
                v1.y = acc_hh[a][nt][3] + acc_q[a][nt][3] + Qs[(cc+1)*132 + r0 + 8];
                *(float2*)(Gout + (long)r0*128 + cc)       = v0;
                *(float2*)(Gout + (long)(r0 + 8)*128 + cc) = v1;
            }
    }

    {
        float tot = ps + __shfl_xor_sync(0xffffffffu, ps, 1);
        if (half == 0) dS[(s*NT + t)*Cc + c0] = tot;
    }
}

// ---------------------------------------------------------------------------
// Kernel B (R8/R13 scalar FFMA2 version)
// ---------------------------------------------------------------------------
__global__ __launch_bounds__(256) void mid_kernel(
    const float* __restrict__ W1a, const float* __restrict__ B1a,
    const float* __restrict__ W2a, const float* __restrict__ B2a,
    const float* __restrict__ Wouta,
    const float* __restrict__ W1b, const float* __restrict__ B1b,
    const float* __restrict__ W2b, const float* __restrict__ B2b,
    const float* __restrict__ Woutb)
{
    extern __shared__ float sm[];
    float* sG  = sm;            // 128*132
    float* sW  = sm + 16896;    // 128*132
    float* sT  = sm + 33792;    // 128*132
    float* sS  = sm + 50688;    // 128
    float* w1s = sm + 50816;    // 128
    float* w2s = sm + 50944;    // 64
    float* nk  = sm + 51008;    // 64

    int s = blockIdx.y;
    const float* W1   = s ? W1b   : W1a;
    const float* B1   = s ? B1b   : B1a;
    const float* W2   = s ? W2b   : W2a;
    const float* B2   = s ? B2b   : B2a;
    const float* Wout = s ? Woutb : Wouta;

    int t = blockIdx.x, tid = threadIdx.x;
    int ty = tid >> 4, tx = tid & 15;
    const float* Gsrc = dG + (long)(s*NT + t)*(Cc*Cc);

    for (int idx = tid; idx < 16384; idx += 256)
        sG[(idx >> 7)*132 + (idx & 127)] = Gsrc[idx];
    for (int idx = tid; idx < 16384; idx += 256)
        sW[(idx & 127)*132 + (idx >> 7)] = W1[idx];      // W1^T[c][o]
    if (tid < 128) sS[tid] = dS[(s*NT + t)*Cc + tid];
    __syncthreads();

    if (tid < 128) {                                      // w1s = W1 s
        float a = 0.f;
        for (int j = 0; j < 128; j++) a = fmaf(sW[j*132 + tid], sS[j], a);
        w1s[tid] = a;
    }

    // T1 = W1 @ G  (store transposed: sT[col][row])
    {
        int i0 = ty*8, c0 = tx*8;
        u64t acc[8][4];
        #pragma unroll
        for (int u = 0; u < 8; u++)
            #pragma unroll
            for (int v = 0; v < 4; v++) acc[u][v] = 0ull;
        for (int j = 0; j < 128; j++) {
            const float* wr = sW + j*132;
            const float* gr = sG + j*132;
            float4 a03 = *(const float4*)(wr + i0);
            float4 a47 = *(const float4*)(wr + i0 + 4);
            ulonglong2 b01 = *(const ulonglong2*)(gr + c0);
            ulonglong2 b23 = *(const ulonglong2*)(gr + c0 + 4);
            u64t as[8] = { f2splat(a03.x), f2splat(a03.y), f2splat(a03.z), f2splat(a03.w),
                           f2splat(a47.x), f2splat(a47.y), f2splat(a47.z), f2splat(a47.w) };
            #pragma unroll
            for (int u = 0; u < 8; u++) {
                f2fma(acc[u][0], as[u], b01.x);
                f2fma(acc[u][1], as[u], b01.y);
                f2fma(acc[u][2], as[u], b23.x);
                f2fma(acc[u][3], as[u], b23.y);
            }
        }
        #pragma unroll
        for (int u = 0; u < 8; u++)
            #pragma unroll
            for (int v = 0; v < 4; v++) {
                float e0, e1; f2unpack(acc[u][v], e0, e1);
                sT[(c0+2*v  )*132 + i0 + u] = e0;
                sT[(c0+2*v+1)*132 + i0 + u] = e1;
            }
    }
    __syncthreads();

    for (int idx = tid; idx < 8192; idx += 256)           // W2^T[c][k]
        sW[(idx & 127)*132 + (idx >> 7)] = W2[idx];
    __syncthreads();
    if (tid < 64) {                                       // w2s = W2 s
        float a = 0.f;
        for (int c = 0; c < 128; c++) a = fmaf(sW[c*132 + tid], sS[c], a);
        w2s[tid] = a;
    }
    __syncthreads();

    // M = T1 @ W2^T + biases -> sG[c][k]
    {
        int i0 = ty*8, k0 = tx*4;
        u64t acc[8][2];
        #pragma unroll
        for (int u = 0; u < 8; u++) { acc[u][0] = 0ull; acc[u][1] = 0ull; }
        for (int c = 0; c < 128; c++) {
            const float* tr = sT + c*132;
            float4 a03 = *(const float4*)(tr + i0);
            float4 a47 = *(const float4*)(tr + i0 + 4);
            ulonglong2 bq = *(const ulonglong2*)(sW + c*132 + k0);
            u64t as[8] = { f2splat(a03.x), f2splat(a03.y), f2splat(a03.z), f2splat(a03.w),
                           f2splat(a47.x), f2splat(a47.y), f2splat(a47.z), f2splat(a47.w) };
            #pragma unroll
            for (int u = 0; u < 8; u++) {
                f2fma(acc[u][0], as[u], bq.x);
                f2fma(acc[u][1], as[u], bq.y);
            }
        }
        float b2v[4];
        #pragma unroll
        for (int v = 0; v < 4; v++) b2v[v] = B2[k0+v];
        #pragma unroll
        for (int u = 0; u < 8; u++) {
            float b1v = B1[i0+u];
            float m0, m1, m2, m3;
            f2unpack(acc[u][0], m0, m1);
            f2unpack(acc[u][1], m2, m3);
            float w1u = w1s[i0+u];
            sG[(i0+u)*132 + k0+0] = m0 + w1u*b2v[0] + b1v*w2s[k0+0] + 1024.f*b1v*b2v[0];
            sG[(i0+u)*132 + k0+1] = m1 + w1u*b2v[1] + b1v*w2s[k0+1] + 1024.f*b1v*b2v[1];
            sG[(i0+u)*132 + k0+2] = m2 + w1u*b2v[2] + b1v*w2s[k0+2] + 1024.f*b1v*b2v[2];
            sG[(i0+u)*132 + k0+3] = m3 + w1u*b2v[3] + b1v*w2s[k0+3] + 1024.f*b1v*b2v[3];
        }
    }
    __syncthreads();

    if (tid < 64) {                                       // column L2 norms
        float ss = 0.f;
        for (int c = 0; c < 128; c++) { float v = sG[c*132 + tid]; ss = fmaf(v, v, ss); }
        nk[tid] = 1.f / (1e-6f + sqrtf(ss));
    }
    __syncthreads();

    for (int idx = tid; idx < 8192; idx += 256) {         // u = M * invnorm
        int c = idx >> 6, kx = idx & 63;
        sG[c*132 + kx] *= nk[kx];
    }
    for (int idx = tid; idx < 16384; idx += 256)          // Wout^T[c][o]
        sW[(idx & 127)*132 + (idx >> 7)] = Wout[idx];
    __syncthreads();

    // A = Wout @ u  -> write bf16 hi/lo A[o][k]
    {
        int o0 = ty*8, k0 = tx*4;
        u64t acc[4][4];
        #pragma unroll
        for (int kk = 0; kk < 4; kk++)
            #pragma unroll
            for (int v = 0; v < 4; v++) acc[kk][v] = 0ull;
        for (int c = 0; c < 128; c++) {
            const float* wr = sW + c*132;
            ulonglong2 a01 = *(const ulonglong2*)(wr + o0);
            ulonglong2 a23 = *(const ulonglong2*)(wr + o0 + 4);
            float4 bq = *(const float4*)(sG + c*132 + k0);
            u64t bs[4] = { f2splat(bq.x), f2splat(bq.y), f2splat(bq.z), f2splat(bq.w) };
            #pragma unroll
            for (int kk = 0; kk < 4; kk++) {
                f2fma(acc[kk][0], a01.x, bs[kk]);
                f2fma(acc[kk][1], a01.y, bs[kk]);
                f2fma(acc[kk][2], a23.x, bs[kk]);
                f2fma(acc[kk][3], a23.y, bs[kk]);
            }
        }
        ush* AH = dAh + ((long)(s*NT + t) << 13);
        ush* AL = dAl + ((long)(s*NT + t) << 13);
        #pragma unroll
        for (int kk = 0; kk < 4; kk++)
            #pragma unroll
            for (int v = 0; v < 4; v++) {
                float e0, e1; f2unpack(acc[kk][v], e0, e1);
                int k = k0 + kk;
                __nv_bfloat16 h0 = __float2bfloat16(e0);
                __nv_bfloat16 h1 = __float2bfloat16(e1);
                AH[(o0+2*v  )*64 + k] = __bfloat16_as_ushort(h0);
                AH[(o0+2*v+1)*64 + k] = __bfloat16_as_ushort(h1);
                AL[(o0+2*v  )*64 + k] = __bfloat16_as_ushort(__float2bfloat16(e0 - __bfloat162float(h0)));
                AL[(o0+2*v+1)*64 + k] = __bfloat16_as_ushort(__float2bfloat16(e1 - __bfloat162float(h1)));
            }
    }
}

// ---------------------------------------------------------------------------
// Kernel C v4: single 256-row X buffer (X1 rows 0-127, X2 rows 128-255);
// ONE fused V GEMM sweep k=0..255; Vraw overlays XH, V hi/lo overlay XL.
// 5 syncs per chunk (vs 6). A in smem, Vraw-smem softmax (R8 style).
// ---------------------------------------------------------------------------
__global__ __launch_bounds__(256) void out_kernel(const float* __restrict__ x1,
                                                  const float* __restrict__ x2,
                                                  const float* __restrict__ Wv,
                                                  const float* __restrict__ bv,
                                                  float* __restrict__ out1,
                                                  float* __restrict__ out2)
{
    extern __shared__ char osm[];
    ush*   sWvH  = (ush*)osm;                    // [64][264]  33792 B
    ush*   sWvL  = (ush*)(osm + 33792);
    ush*   sAH   = (ush*)(osm + 67584);          // [2][128][72] 36864 B
    ush*   sAL   = (ush*)(osm + 104448);
    ush*   sXH   = (ush*)(osm + 141312);         // [256][72] 36864 B
    ush*   sXL   = (ush*)(osm + 178176);         // [256][72]
    float* sVraw = (float*)(osm + 141312);       // overlays XH: [64][72] fp32
    ush*   sVH   = (ush*)(osm + 178176);         // overlays XL: [64][72]
    ush*   sVL   = (ush*)(osm + 178176 + 9216);
    float* sbv   = (float*)(osm + 215040);       // 64

    uint32_t uWvH = s2u(sWvH), uWvL = s2u(sWvL);
    uint32_t uAH = s2u(sAH), uAL = s2u(sAL);
    uint32_t uXH = s2u(sXH), uXL = s2u(sXL);
    uint32_t uVH = s2u(sVH), uVL = s2u(sVL);

    int t = blockIdx.x, halfy = blockIdx.y;
    int b  = t >> 6, q = t & 63;
    int pi = q >> 3, pj = q & 7;
    long base0 = (long)b*Cc*HW + (long)(pi*32)*Ww + pj*32;
    int li0 = halfy*16;

    int tid = threadIdx.x, wid = tid >> 5, lane = tid & 31;

    // ---- load Wv hi/lo ----
    for (int idx = tid; idx < 16384; idx += 256) {
        int r = idx >> 8, c = idx & 255;
        float v = Wv[idx];
        __nv_bfloat16 h = __float2bfloat16(v);
        sWvH[r*264 + c] = __bfloat16_as_ushort(h);
        sWvL[r*264 + c] = __bfloat16_as_ushort(__float2bfloat16(v - __bfloat162float(h)));
    }
    // ---- load A hi/lo (both streams) ----
    {
        const ush* A1h = dAh + ((long)t << 13);
        const ush* A2h = dAh + ((long)(NT + t) << 13);
        const ush* A1l = dAl + ((long)t << 13);
        const ush* A2l = dAl + ((long)(NT + t) << 13);
        for (int idx = tid; idx < 8192; idx += 256) {
            int o = idx >> 6, k = idx & 63;
            sAH[o*72 + k]        = A1h[idx];
            sAH[9216 + o*72 + k] = A2h[idx];
            sAL[o*72 + k]        = A1l[idx];
            sAL[9216 + o*72 + k] = A2l[idx];
        }
    }
    if (tid < 64) sbv[tid] = bv[tid];

    // lane addressing
    uint32_t aRow = (uint32_t)(lane & 15);
    uint32_t aKof = (uint32_t)((lane >> 4) << 3);
    uint32_t g = (uint32_t)(lane >> 3), rr8 = (uint32_t)(lane & 7);
    uint32_t tKrow = ((g & 1u) << 3) + rr8;     // k offset within k16 block
    uint32_t tNcol = (g >> 1) << 3;             // n offset within n16 block
    int grp = lane >> 2, tix = lane & 3;

    // X loader mapping: thread handles channel c0, local row h2
    int c0 = tid >> 1, h2 = tid & 1;
    const float* x1base = x1 + base0 + (long)c0*HW;
    const float* x2base = x2 + base0 + (long)c0*HW;
    uint32_t xo1 = ((uint32_t)c0*72u + (uint32_t)h2*32u)*2u;           // X1 rows 0..127
    uint32_t xo2 = (((uint32_t)(128 + c0))*72u + (uint32_t)h2*32u)*2u; // X2 rows 128..255

    // V GEMM warp tiling: m0 over k-dim(64), n0 over l(64)
    int vm0 = (wid & 3)*16, vn0 = (wid >> 2)*32;
    // out GEMM warp tiling
    int st = wid >> 2, om0 = (wid & 3)*32;
    uint32_t uA_H = uAH + (uint32_t)st*9216u*2u;
    uint32_t uA_L = uAL + (uint32_t)st*9216u*2u;
    float* outp = st ? out2 : out1;

    // prefetch chunk 0 (both streams)
    float4 p1[8], p2[8];
    {
        const float4* s1 = (const float4*)(x1base + (long)(li0 + h2)*Ww);
        const float4* s2 = (const float4*)(x2base + (long)(li0 + h2)*Ww);
        #pragma unroll
        for (int j = 0; j < 8; j++) { p1[j] = s1[j]; p2[j] = s2[j]; }
    }
    // store chunk 0 (X region disjoint from Wv/A stores above; no sync needed yet)
    #pragma unroll
    for (int j = 0; j < 8; j++) {
        float4 v = p1[j];
        __nv_bfloat16 hx = __float2bfloat16(v.x), hy = __float2bfloat16(v.y),
                      hz = __float2bfloat16(v.z), hw = __float2bfloat16(v.w);
        uint32_t off = xo1 + 8u*j;
        *(uint2*)((char*)sXH + off) = make_uint2(bfp(hx, hy), bfp(hz, hw));
        *(uint2*)((char*)sXL + off) = make_uint2(
            bfp2(v.x - __bfloat162float(hx), v.y - __bfloat162float(hy)),
            bfp2(v.z - __bfloat162float(hz), v.w - __bfloat162float(hw)));
        v = p2[j];
        hx = __float2bfloat16(v.x); hy = __float2bfloat16(v.y);
        hz = __float2bfloat16(v.z); hw = __float2bfloat16(v.w);
        off = xo2 + 8u*j;
        *(uint2*)((char*)sXH + off) = make_uint2(bfp(hx, hy), bfp(hz, hw));
        *(uint2*)((char*)sXL + off) = make_uint2(
            bfp2(v.x - __bfloat162float(hx), v.y - __bfloat162float(hy)),
            bfp2(v.z - __bfloat162float(hz), v.w - __bfloat162float(hw)));
    }
    __syncthreads();

    for (int ch = 0; ch < 8; ch++) {
        int lrow = li0 + 2*ch;

        // ---- V GEMM, k = 0..255 in one fused sweep ----
        float accV[4][4];
        #pragma unroll
        for (int nt = 0; nt < 4; nt++)
            #pragma unroll
            for (int e = 0; e < 4; e++) accV[nt][e] = 0.f;

        #pragma unroll 2
        for (int ks = 0; ks < 16; ks++) {
            uint32_t kx = (uint32_t)(ks*16);
            uint32_t ah[4], al[4], bh[8], bl[8];
            uint32_t ao = ((uint32_t)vm0 + aRow)*264u + kx + aKof;
            ldm4(ah, uWvH + ao*2u);
            ldm4(al, uWvL + ao*2u);
            uint32_t bo0 = (kx + tKrow)*72u + (uint32_t)vn0 + tNcol;
            ldm4t(bh,     uXH + bo0*2u);
            ldm4t(bh + 4, uXH + (bo0 + 16u)*2u);
            ldm4t(bl,     uXL + bo0*2u);
            ldm4t(bl + 4, uXL + (bo0 + 16u)*2u);
            #pragma unroll
            for (int nt = 0; nt < 4; nt++) {
                mma16816(accV[nt], ah, bh + 2*nt);
                mma16816(accV[nt], ah, bl + 2*nt);
                mma16816(accV[nt], al, bh + 2*nt);
            }
        }
        __syncthreads();   // S1: all X reads done; X region free for Vraw/V

        // write V_raw + bias (into XH overlay)
        {
            float bv0 = sbv[vm0 + grp], bv1 = sbv[vm0 + grp + 8];
            #pragma unroll
            for (int nt = 0; nt < 4; nt++) {
                int col = vn0 + nt*8 + tix*2;
                float2 v0; v0.x = accV[nt][0] + bv0; v0.y = accV[nt][1] + bv0;
                float2 v1; v1.x = accV[nt][2] + bv1; v1.y = accV[nt][3] + bv1;
                *(float2*)(sVraw + (vm0 + grp)*72 + col)     = v0;
                *(float2*)(sVraw + (vm0 + grp + 8)*72 + col) = v1;
            }
        }
        __syncthreads();   // S2: Vraw complete

        // softmax over k per column; emit V hi/lo bf16 (into XL overlay)
        {
            int col = wid*8 + (lane >> 2);
            int kg = lane & 3;
            float vals[16];
            float m = -1e30f;
            #pragma unroll
            for (int i = 0; i < 16; i++) {
                vals[i] = sVraw[(i*4 + kg)*72 + col];
                m = fmaxf(m, vals[i]);
            }
            m = fmaxf(m, __shfl_xor_sync(0xffffffffu, m, 1));
            m = fmaxf(m, __shfl_xor_sync(0xffffffffu, m, 2));
            float ssum = 0.f;
            #pragma unroll
            for (int i = 0; i < 16; i++) { float e = __expf(vals[i] - m); vals[i] = e; ssum += e; }
            ssum += __shfl_xor_sync(0xffffffffu, ssum, 1);
            ssum += __shfl_xor_sync(0xffffffffu, ssum, 2);
            float inv = 1.f / ssum;
            #pragma unroll
            for (int i = 0; i < 16; i++) {
                float v = vals[i]*inv;
                __nv_bfloat16 h = __float2bfloat16(v);
                int idx = (i*4 + kg)*72 + col;
                sVH[idx] = __bfloat16_as_ushort(h);
                sVL[idx] = __bfloat16_as_ushort(__float2bfloat16(v - __bfloat162float(h)));
            }
        }
        __syncthreads();   // S3: V hi/lo ready

        // ---- out GEMM + epilogue; prefetch next chunk (both streams) ----
        {
            if (ch < 7) {
                const float4* s1 = (const float4*)(x1base + (long)(lrow + 2 + h2)*Ww);
                const float4* s2 = (const float4*)(x2base + (long)(lrow + 2 + h2)*Ww);
                #pragma unroll
                for (int j = 0; j < 8; j++) { p1[j] = s1[j]; p2[j] = s2[j]; }
            }

            float accO[2][8][4];
            #pragma unroll
            for (int a = 0; a < 2; a++)
                #pragma unroll
                for (int nt = 0; nt < 8; nt++)
                    #pragma unroll
                    for (int e = 0; e < 4; e++) accO[a][nt][e] = 0.f;

            #pragma unroll
            for (int ks = 0; ks < 4; ks++) {
                uint32_t k0 = (uint32_t)(ks*16);
                uint32_t ah[2][4], al[2][4], bh[16], bl[16];
                #pragma unroll
                for (int a = 0; a < 2; a++) {
                    uint32_t ao = ((uint32_t)(om0 + a*16) + aRow)*72u + k0 + aKof;
                    ldm4(ah[a], uA_H + ao*2u);
                    ldm4(al[a], uA_L + ao*2u);
                }
                #pragma unroll
                for (int qq = 0; qq < 4; qq++) {
                    uint32_t bo = (k0 + tKrow)*72u + (uint32_t)(qq*16) + tNcol;
                    ldm4t(bh + 4*qq, uVH + bo*2u);
                    ldm4t(bl + 4*qq, uVL + bo*2u);
                }
                #pragma unroll
                for (int a = 0; a < 2; a++)
                    #pragma unroll
                    for (int nt = 0; nt < 8; nt++) {
                        const uint32_t* ph = bh + 4*(nt >> 1) + 2*(nt & 1);
                        const uint32_t* pl = bl + 4*(nt >> 1) + 2*(nt & 1);
                        mma16816(accO[a][nt], ah[a], ph);
                        mma16816(accO[a][nt], ah[a], pl);
                        mma16816(accO[a][nt], al[a], ph);
                    }
            }

            #pragma unroll
            for (int a = 0; a < 2; a++)
                #pragma unroll
                for (int nt = 0; nt < 8; nt++) {
                    int o = om0 + a*16 + grp;
                    int l = nt*8 + tix*2;
                    int lr = l >> 5, lj = l & 31;
                    long gaddr = ((long)(b*Cc + o)*Hh + (pi*32 + lrow + lr))*Ww + pj*32 + lj;
                    float2 v0; v0.x = accO[a][nt][0]; v0.y = accO[a][nt][1];
                    float2 v1; v1.x = accO[a][nt][2]; v1.y = accO[a][nt][3];
                    *(float2*)(outp + gaddr)              = v0;
                    *(float2*)(outp + gaddr + 8l*HW)      = v1;
                }
        }
        __syncthreads();   // S4: out GEMM done (V reads complete); X region free

        // store next chunk X (overwrites Vraw / V hi-lo overlays)
        if (ch < 7) {
            #pragma unroll
            for (int j = 0; j < 8; j++) {
                float4 v = p1[j];
                __nv_bfloat16 hx = __float2bfloat16(v.x), hy = __float2bfloat16(v.y),
                              hz = __float2bfloat16(v.z), hw = __float2bfloat16(v.w);
                uint32_t off = xo1 + 8u*j;
                *(uint2*)((char*)sXH + off) = make_uint2(bfp(hx, hy), bfp(hz, hw));
                *(uint2*)((char*)sXL + off) = make_uint2(
                    bfp2(v.x - __bfloat162float(hx), v.y - __bfloat162float(hy)),
                    bfp2(v.z - __bfloat162float(hz), v.w - __bfloat162float(hw)));
                v = p2[j];
                hx = __float2bfloat16(v.x); hy = __float2bfloat16(v.y);
                hz = __float2bfloat16(v.z); hw = __float2bfloat16(v.w);
                off = xo2 + 8u*j;
                *(uint2*)((char*)sXH + off) = make_uint2(bfp(hx, hy), bfp(hz, hw));
                *(uint2*)((char*)sXL + off) = make_uint2(
                    bfp2(v.x - __bfloat162float(hx), v.y - __bfloat162float(hy)),
                    bfp2(v.z - __bfloat162float(hz), v.w - __bfloat162float(hw)));
            }
            __syncthreads();   // S5: next X staged
        }
    }
}

extern "C" void kernel_launch(void* const* d_in, const int* in_sizes, int n_in,
                              void* d_out, int out_size)
{
    const float* x1     = (const float*)d_in[0];
    const float* x2     = (const float*)d_in[1];
    const float* w_v    = (const float*)d_in[2];
    const float* b_v    = (const float*)d_in[3];
    const float* w1_1   = (const float*)d_in[4];
    const float* b1_1   = (const float*)d_in[5];
    const float* w2_1   = (const float*)d_in[6];
    const float* b2_1   = (const float*)d_in[7];
    const float* w_out1 = (const float*)d_in[8];
    const float* w1_2   = (const float*)d_in[9];
    const float* b1_2   = (const float*)d_in[10];
    const float* w2_2   = (const float*)d_in[11];
    const float* b2_2   = (const float*)d_in[12];
    const float* w_out2 = (const float*)d_in[13];
    (void)in_sizes; (void)n_in; (void)out_size;

    float* out1 = (float*)d_out;
    float* out2 = out1 + (size_t)Bb*Cc*HW;

    cudaFuncSetAttribute(gram_kernel, cudaFuncAttributeMaxDynamicSharedMemorySize, GRAM2_SMEM);
    cudaFuncSetAttribute(mid_kernel, cudaFuncAttributeMaxDynamicSharedMemorySize, MID_SMEM);
    cudaFuncSetAttribute(out_kernel, cudaFuncAttributeMaxDynamicSharedMemorySize, OUT4_SMEM);

    gram_kernel<<<dim3(NT, 2), 256, GRAM2_SMEM>>>(x1, x2);
    mid_kernel<<<dim3(NT, 2), 256, MID_SMEM>>>(w1_1, b1_1, w2_1, b2_1, w_out1,
                                               w1_2, b1_2, w2_2, b2_2, w_out2);
    out_kernel<<<dim3(NT, 2), 256, OUT4_SMEM>>>(x1, x2, w_v, b_v, out1, out2);
}

// round 16
// speedup vs baseline: 1.1419x; 1.1419x over previous
#include <cuda_runtime.h>
#include <cuda_bf16.h>
#include <math.h>
#include <stdint.h>

#define Bb 4
#define Cc 128
#define Kk 64
#define Hh 256
#define Ww 256
#define HW (Hh*Ww)
#define NT 256          // B * P*P tiles
#define MID_SMEM_FLOATS 51072
#define MID_SMEM (MID_SMEM_FLOATS*4)
#define LDB 72          // bf16 elements per smem row (64 data + 8 pad)
#define GRAM2_SMEM 73728
#define OUT2_SMEM 215296

typedef unsigned short ush;

// ---- packed fp32x2 helpers (FFMA2) ----
typedef unsigned long long u64t;
__device__ __forceinline__ u64t f2pack(float lo, float hi){
    u64t r; asm("mov.b64 %0, {%1,%2};" : "=l"(r) : "f"(lo), "f"(hi)); return r;
}
__device__ __forceinline__ u64t f2splat(float v){ return f2pack(v, v); }
__device__ __forceinline__ void f2unpack(u64t v, float& lo, float& hi){
    asm("mov.b64 {%0,%1}, %2;" : "=f"(lo), "=f"(hi) : "l"(v));
}
__device__ __forceinline__ void f2fma(u64t& d, u64t a, u64t b){
    asm("fma.rn.f32x2 %0, %1, %2, %3;" : "=l"(d) : "l"(a), "l"(b), "l"(d));
}

// ---- mma.sync helpers (arch-neutral tensor path) ----
__device__ __forceinline__ uint32_t s2u(const void* p){
    uint32_t a;
    asm("{ .reg .u64 t; cvta.to.shared.u64 t, %1; cvt.u32.u64 %0, t; }" : "=r"(a) : "l"(p));
    return a;
}
__device__ __forceinline__ void ldm4(uint32_t* d, uint32_t addr){
    asm volatile("ldmatrix.sync.aligned.m8n8.x4.shared.b16 {%0,%1,%2,%3}, [%4];"
        : "=r"(d[0]), "=r"(d[1]), "=r"(d[2]), "=r"(d[3]) : "r"(addr));
}
__device__ __forceinline__ void ldm4t(uint32_t* d, uint32_t addr){
    asm volatile("ldmatrix.sync.aligned.m8n8.x4.trans.shared.b16 {%0,%1,%2,%3}, [%4];"
        : "=r"(d[0]), "=r"(d[1]), "=r"(d[2]), "=r"(d[3]) : "r"(addr));
}
__device__ __forceinline__ void mma16816(float* c, const uint32_t* a, const uint32_t* b){
    asm volatile("mma.sync.aligned.m16n8k16.row.col.f32.bf16.bf16.f32 "
        "{%0,%1,%2,%3}, {%4,%5,%6,%7}, {%8,%9}, {%0,%1,%2,%3};"
        : "+f"(c[0]), "+f"(c[1]), "+f"(c[2]), "+f"(c[3])
        : "r"(a[0]), "r"(a[1]), "r"(a[2]), "r"(a[3]), "r"(b[0]), "r"(b[1]));
}
__device__ __forceinline__ uint32_t bfp(__nv_bfloat16 a, __nv_bfloat16 b){
    return ((uint32_t)__bfloat16_as_ushort(b) << 16) | (uint32_t)__bfloat16_as_ushort(a);
}
__device__ __forceinline__ uint32_t bfp2(float a, float b){
    return bfp(__float2bfloat16(a), __float2bfloat16(b));
}

// Scratch (allocation-free rule: __device__ globals)
__device__ float dG[2*NT*Cc*Cc];   // per (stream,tile) Gram 128x128
__device__ float dS[2*NT*Cc];      // per (stream,tile) row sums
__device__ ush   dAh[2*NT*Cc*Kk];  // A hi bf16, layout [s][t][o=128][k=64]
__device__ ush   dAl[2*NT*Cc*Kk];  // A lo bf16

// ---------------------------------------------------------------------------
// Kernel A (HMMA, R13 version): G = X X^T = HH + Q + Q^T.
// ---------------------------------------------------------------------------
__global__ __launch_bounds__(256) void gram_kernel(const float* __restrict__ x1,
                                                   const float* __restrict__ x2)
{
    extern __shared__ char gsm[];
    uint32_t gb = s2u(gsm);

    int t = blockIdx.x, s = blockIdx.y;
    const float* x = s ? x2 : x1;
    int b = t >> 6, q = t & 63;
    int pi = q >> 3, pj = q & 7;
    long base0 = (long)b*Cc*HW + (long)(pi*32)*Ww + pj*32;

    int tid = threadIdx.x, wid = tid >> 5, lane = tid & 31;
    int c0 = tid >> 1, half = tid & 1;
    const float* rowbase = x + base0 + (long)c0*HW + (long)half*Ww;

    int wm = wid & 3, wn = wid >> 2;
    int m0 = wm*32, n0 = wn*64;

    float acc_hh[2][8][4], acc_q[2][8][4];
    #pragma unroll
    for (int a = 0; a < 2; a++)
        #pragma unroll
        for (int nt = 0; nt < 8; nt++)
            #pragma unroll
            for (int e = 0; e < 4; e++) { acc_hh[a][nt][e] = 0.f; acc_q[a][nt][e] = 0.f; }

    float ps = 0.f;
    float4 pref[8];
    {
        const float4* src = (const float4*)rowbase;
        #pragma unroll
        for (int j = 0; j < 8; j++) pref[j] = src[j];
    }

    uint32_t aRow = (uint32_t)(lane & 15);
    uint32_t aKof = (uint32_t)((lane >> 4) << 3);
    uint32_t bRow = (uint32_t)((lane & 7) + ((lane >> 4) << 3));
    uint32_t bKof = (uint32_t)(((lane >> 3) & 1) << 3);

    uint32_t wo = ((uint32_t)c0*LDB + (uint32_t)half*32u)*2u;

    #pragma unroll
    for (int j = 0; j < 8; j++) {
        float4 v = pref[j];
        ps += (v.x + v.y) + (v.z + v.w);
        __nv_bfloat16 hx = __float2bfloat16(v.x), hy = __float2bfloat16(v.y),
                      hz = __float2bfloat16(v.z), hw = __float2bfloat16(v.w);
        uint32_t off = wo + 8u*j;
        *(uint2*)(gsm + off) = make_uint2(bfp(hx, hy), bfp(hz, hw));
        *(uint2*)(gsm + 18432 + off) = make_uint2(
            bfp2(v.x - __bfloat162float(hx), v.y - __bfloat162float(hy)),
            bfp2(v.z - __bfloat162float(hz), v.w - __bfloat162float(hw)));
    }
    {
        const float4* src = (const float4*)(rowbase + (long)2*Ww);
        #pragma unroll
        for (int j = 0; j < 8; j++) pref[j] = src[j];
    }
    __syncthreads();

    for (int ch = 0; ch < 16; ch++) {
        uint32_t hiB = gb + (uint32_t)(ch & 1)*36864u;
        uint32_t loB = hiB + 18432u;

        #pragma unroll
        for (int ks = 0; ks < 4; ks++) {
            uint32_t k0 = (uint32_t)(ks*16);
            uint32_t ahi[2][4], bhi[8][2], blo[8][2];
            #pragma unroll
            for (int a = 0; a < 2; a++) {
                uint32_t eo = ((uint32_t)(m0 + a*16) + aRow)*LDB + k0 + aKof;
                ldm4(ahi[a], hiB + eo*2u);
            }
            #pragma unroll
            for (int p = 0; p < 4; p++) {
                uint32_t eo = ((uint32_t)(n0 + p*16) + bRow)*LDB + k0 + bKof;
                uint32_t r[4];
                ldm4(r, hiB + eo*2u);
                bhi[2*p][0] = r[0]; bhi[2*p][1] = r[1];
                bhi[2*p+1][0] = r[2]; bhi[2*p+1][1] = r[3];
                ldm4(r, loB + eo*2u);
                blo[2*p][0] = r[0]; blo[2*p][1] = r[1];
                blo[2*p+1][0] = r[2]; blo[2*p+1][1] = r[3];
            }
            #pragma unroll
            for (int a = 0; a < 2; a++)
                #pragma unroll
                for (int nt = 0; nt < 8; nt++) {
                    mma16816(acc_hh[a][nt], ahi[a], bhi[nt]);
                    mma16816(acc_q[a][nt],  ahi[a], blo[nt]);
                }
        }

        if (ch < 15) {
            char* dsth = gsm + ((ch + 1) & 1)*36864;
            #pragma unroll
            for (int j = 0; j < 8; j++) {
                float4 v = pref[j];
                ps += (v.x + v.y) + (v.z + v.w);
                __nv_bfloat16 hx = __float2bfloat16(v.x), hy = __float2bfloat16(v.y),
                              hz = __float2bfloat16(v.z), hw = __float2bfloat16(v.w);
                uint32_t off = wo + 8u*j;
                *(uint2*)(dsth + off) = make_uint2(bfp(hx, hy), bfp(hz, hw));
                *(uint2*)(dsth + 18432 + off) = make_uint2(
                    bfp2(v.x - __bfloat162float(hx), v.y - __bfloat162float(hy)),
                    bfp2(v.z - __bfloat162float(hz), v.w - __bfloat162float(hw)));
            }
            if (ch < 14) {
                const float4* src = (const float4*)(rowbase + (long)((ch + 2)*2)*Ww);
                #pragma unroll
                for (int j = 0; j < 8; j++) pref[j] = src[j];
            }
        }
        __syncthreads();
    }

    {
        float* Qs = (float*)gsm;
        int grp = lane >> 2, tix = lane & 3;
        #pragma unroll
        for (int a = 0; a < 2; a++)
            #pragma unroll
            for (int nt = 0; nt < 8; nt++) {
                int r0 = m0 + a*16 + grp, cc = n0 + nt*8 + tix*2;
                Qs[r0*132 + cc]       = acc_q[a][nt][0];
                Qs[r0*132 + cc + 1]   = acc_q[a][nt][1];
                Qs[(r0+8)*132 + cc]   = acc_q[a][nt][2];
                Qs[(r0+8)*132 + cc+1] = acc_q[a][nt][3];
            }
        __syncthreads();
        float* Gout = dG + (long)(s*NT + t)*(Cc*Cc);
        #pragma unroll
        for (int a = 0; a < 2; a++)
            #pragma unroll
            for (int nt = 0; nt < 8; nt++) {
                int r0 = m0 + a*16 + grp, cc = n0 + nt*8 + tix*2;
                float2 v0, v1;
                v0.x = acc_hh[a][nt][0] + acc_q[a][nt][0] + Qs[cc*132 + r0];
                v0.y = acc_hh[a][nt][1] + acc_q[a][nt][1] + Qs[(cc+1)*132 + r0];
                v1.x = acc_hh[a][nt][2] + acc_q[a][nt][2] + Qs[cc*132 + r0 + 8];
                v1.y = acc_hh[a][nt][3] + acc_q[a][nt][3] + Qs[(cc+1)*132 + r0 + 8];
                *(float2*)(Gout + (long)r0*128 + cc)       = v0;
                *(float2*)(Gout + (long)(r0 + 8)*128 + cc) = v1;
            }
    }

    {
        float tot = ps + __shfl_xor_sync(0xffffffffu, ps, 1);
        if (half == 0) dS[(s*NT + t)*Cc + c0] = tot;
    }
}

// ---------------------------------------------------------------------------
// Kernel B (reassociated): P = G W2^T (via G symmetry), M = W1 P + rank-1
// bias terms; u = l2norm; A = Wout u -> dAh/dAl bf16 hi/lo [o][k].
// 33% fewer GEMM FLOPs than the T1 = W1 G ordering.
// ---------------------------------------------------------------------------
__global__ __launch_bounds__(256) void mid_kernel(
    const float* __restrict__ W1a, const float* __restrict__ B1a,
    const float* __restrict__ W2a, const float* __restrict__ B2a,
    const float* __restrict__ Wouta,
    const float* __restrict__ W1b, const float* __restrict__ B1b,
    const float* __restrict__ W2b, const float* __restrict__ B2b,
    const float* __restrict__ Woutb)
{
    extern __shared__ float sm[];
    float* sG  = sm;            // G then M/u  128*132
    float* sW  = sm + 16896;    // W2^T -> W1^T -> Wout^T
    float* sT  = sm + 33792;    // P [c][k]
    float* sS  = sm + 50688;    // 128
    float* w1s = sm + 50816;    // 128
    float* w2s = sm + 50944;    // 64
    float* nk  = sm + 51008;    // 64

    int s = blockIdx.y;
    const float* W1   = s ? W1b   : W1a;
    const float* B1   = s ? B1b   : B1a;
    const float* W2   = s ? W2b   : W2a;
    const float* B2   = s ? B2b   : B2a;
    const float* Wout = s ? Woutb : Wouta;

    int t = blockIdx.x, tid = threadIdx.x;
    int ty = tid >> 4, tx = tid & 15;
    const float* Gsrc = dG + (long)(s*NT + t)*(Cc*Cc);

    for (int idx = tid; idx < 16384; idx += 256)
        sG[(idx >> 7)*132 + (idx & 127)] = Gsrc[idx];
    for (int idx = tid; idx < 8192; idx += 256)           // W2^T[c][k]
        sW[(idx & 127)*132 + (idx >> 7)] = W2[idx];
    if (tid < 128) sS[tid] = dS[(s*NT + t)*Cc + tid];
    __syncthreads();

    if (tid < 64) {                                       // w2s = W2 s
        float a = 0.f;
        for (int c = 0; c < 128; c++) a = fmaf(sW[c*132 + tid], sS[c], a);
        w2s[tid] = a;
    }

    // P = G @ W2^T  (G symmetric: P[c][k] = sum_j G[j][c] * W2^T[j][k])
    {
        int i0 = ty*8, k0 = tx*4;
        u64t acc[8][2];
        #pragma unroll
        for (int u = 0; u < 8; u++) { acc[u][0] = 0ull; acc[u][1] = 0ull; }
        for (int j = 0; j < 128; j++) {
            const float* gr = sG + j*132;
            float4 a03 = *(const float4*)(gr + i0);
            float4 a47 = *(const float4*)(gr + i0 + 4);
            ulonglong2 bq = *(const ulonglong2*)(sW + j*132 + k0);
            u64t as[8] = { f2splat(a03.x), f2splat(a03.y), f2splat(a03.z), f2splat(a03.w),
                           f2splat(a47.x), f2splat(a47.y), f2splat(a47.z), f2splat(a47.w) };
            #pragma unroll
            for (int u = 0; u < 8; u++) {
                f2fma(acc[u][0], as[u], bq.x);
                f2fma(acc[u][1], as[u], bq.y);
            }
        }
        #pragma unroll
        for (int u = 0; u < 8; u++) {
            float e0, e1, e2, e3;
            f2unpack(acc[u][0], e0, e1);
            f2unpack(acc[u][1], e2, e3);
            float4 pv; pv.x = e0; pv.y = e1; pv.z = e2; pv.w = e3;
            *(float4*)(sT + (i0+u)*132 + k0) = pv;
        }
    }
    __syncthreads();

    for (int idx = tid; idx < 16384; idx += 256)          // W1^T[c][o]
        sW[(idx & 127)*132 + (idx >> 7)] = W1[idx];
    __syncthreads();
    if (tid < 128) {                                      // w1s = W1 s
        float a = 0.f;
        for (int j = 0; j < 128; j++) a = fmaf(sW[j*132 + tid], sS[j], a);
        w1s[tid] = a;
    }
    __syncthreads();

    // M = W1 @ P + biases -> sG[i][k]
    {
        int i0 = ty*8, k0 = tx*4;
        u64t acc[8][2];
        #pragma unroll
        for (int u = 0; u < 8; u++) { acc[u][0] = 0ull; acc[u][1] = 0ull; }
        for (int c = 0; c < 128; c++) {
            const float* wr = sW + c*132;
            float4 a03 = *(const float4*)(wr + i0);
            float4 a47 = *(const float4*)(wr + i0 + 4);
            ulonglong2 bq = *(const ulonglong2*)(sT + c*132 + k0);
            u64t as[8] = { f2splat(a03.x), f2splat(a03.y), f2splat(a03.z), f2splat(a03.w),
                           f2splat(a47.x), f2splat(a47.y), f2splat(a47.z), f2splat(a47.w) };
            #pragma unroll
            for (int u = 0; u < 8; u++) {
                f2fma(acc[u][0], as[u], bq.x);
                f2fma(acc[u][1], as[u], bq.y);
            }
        }
        float b2v[4];
        #pragma unroll
        for (int v = 0; v < 4; v++) b2v[v] = B2[k0+v];
        #pragma unroll
        for (int u = 0; u < 8; u++) {
            float b1v = B1[i0+u];
            float m0, m1, m2, m3;
            f2unpack(acc[u][0], m0, m1);
            f2unpack(acc[u][1], m2, m3);
            float w1u = w1s[i0+u];
            sG[(i0+u)*132 + k0+0] = m0 + w1u*b2v[0] + b1v*w2s[k0+0] + 1024.f*b1v*b2v[0];
            sG[(i0+u)*132 + k0+1] = m1 + w1u*b2v[1] + b1v*w2s[k0+1] + 1024.f*b1v*b2v[1];
            sG[(i0+u)*132 + k0+2] = m2 + w1u*b2v[2] + b1v*w2s[k0+2] + 1024.f*b1v*b2v[2];
            sG[(i0+u)*132 + k0+3] = m3 + w1u*b2v[3] + b1v*w2s[k0+3] + 1024.f*b1v*b2v[3];
        }
    }
    __syncthreads();

    if (tid < 64) {                                       // column L2 norms
        float ss = 0.f;
        for (int c = 0; c < 128; c++) { float v = sG[c*132 + tid]; ss = fmaf(v, v, ss); }
        nk[tid] = 1.f / (1e-6f + sqrtf(ss));
    }
    __syncthreads();

    for (int idx = tid; idx < 8192; idx += 256) {         // u = M * invnorm
        int c = idx >> 6, kx = idx & 63;
        sG[c*132 + kx] *= nk[kx];
    }
    for (int idx = tid; idx < 16384; idx += 256)          // Wout^T[c][o]
        sW[(idx & 127)*132 + (idx >> 7)] = Wout[idx];
    __syncthreads();

    // A = Wout @ u  -> write bf16 hi/lo A[o][k]
    {
        int o0 = ty*8, k0 = tx*4;
        u64t acc[4][4];
        #pragma unroll
        for (int kk = 0; kk < 4; kk++)
            #pragma unroll
            for (int v = 0; v < 4; v++) acc[kk][v] = 0ull;
        for (int c = 0; c < 128; c++) {
            const float* wr = sW + c*132;
            ulonglong2 a01 = *(const ulonglong2*)(wr + o0);
            ulonglong2 a23 = *(const ulonglong2*)(wr + o0 + 4);
            float4 bq = *(const float4*)(sG + c*132 + k0);
            u64t bs[4] = { f2splat(bq.x), f2splat(bq.y), f2splat(bq.z), f2splat(bq.w) };
            #pragma unroll
            for (int kk = 0; kk < 4; kk++) {
                f2fma(acc[kk][0], a01.x, bs[kk]);
                f2fma(acc[kk][1], a01.y, bs[kk]);
                f2fma(acc[kk][2], a23.x, bs[kk]);
                f2fma(acc[kk][3], a23.y, bs[kk]);
            }
        }
        ush* AH = dAh + ((long)(s*NT + t) << 13);
        ush* AL = dAl + ((long)(s*NT + t) << 13);
        #pragma unroll
        for (int kk = 0; kk < 4; kk++)
            #pragma unroll
            for (int v = 0; v < 4; v++) {
                float e0, e1; f2unpack(acc[kk][v], e0, e1);
                int k = k0 + kk;
                __nv_bfloat16 h0 = __float2bfloat16(e0);
                __nv_bfloat16 h1 = __float2bfloat16(e1);
                AH[(o0+2*v  )*64 + k] = __bfloat16_as_ushort(h0);
                AH[(o0+2*v+1)*64 + k] = __bfloat16_as_ushort(h1);
                AL[(o0+2*v  )*64 + k] = __bfloat16_as_ushort(__float2bfloat16(e0 - __bfloat162float(h0)));
                AL[(o0+2*v+1)*64 + k] = __bfloat16_as_ushort(__float2bfloat16(e1 - __bfloat162float(h1)));
            }
    }
}

// ---------------------------------------------------------------------------
// Kernel C (R8/R13 HMMA version, unchanged): per (tile, half):
// V = softmax_K(Wv [X1;X2] + bv), Out1 = A1 V, Out2 = A2 V.
// ---------------------------------------------------------------------------
__global__ __launch_bounds__(256) void out_kernel(const float* __restrict__ x1,
                                                  const float* __restrict__ x2,
                                                  const float* __restrict__ Wv,
                                                  const float* __restrict__ bv,
                                                  float* __restrict__ out1,
                                                  float* __restrict__ out2)
{
    extern __shared__ char osm[];
    ush*   sWvH  = (ush*)osm;                  // [64][264]
    ush*   sWvL  = sWvH + 64*264;
    ush*   sAH   = sWvL + 64*264;              // [2][128][72]
    ush*   sAL   = sAH + 2*128*72;
    ush*   sXH   = sAL + 2*128*72;             // [128][72]
    ush*   sXL   = sXH + 128*72;
    ush*   sVH   = sXL + 128*72;               // [64][72]
    ush*   sVL   = sVH + 64*72;
    float* sVraw = (float*)(sVL + 64*72);      // [64][72]
    float* sbv   = sVraw + 64*72;              // 64

    uint32_t uWvH = s2u(sWvH), uWvL = s2u(sWvL);
    uint32_t uAH = s2u(sAH), uAL = s2u(sAL);
    uint32_t uXH = s2u(sXH), uXL = s2u(sXL);
    uint32_t uVH = s2u(sVH), uVL = s2u(sVL);

    int t = blockIdx.x, halfy = blockIdx.y;
    int b  = t >> 6, q = t & 63;
    int pi = q >> 3, pj = q & 7;
    long base0 = (long)b*Cc*HW + (long)(pi*32)*Ww + pj*32;
    int li0 = halfy*16;

    int tid = threadIdx.x, wid = tid >> 5, lane = tid & 31;

    for (int idx = tid; idx < 16384; idx += 256) {
        int r = idx >> 8, c = idx & 255;
        float v = Wv[idx];
        __nv_bfloat16 h = __float2bfloat16(v);
        sWvH[r*264 + c] = __bfloat16_as_ushort(h);
        sWvL[r*264 + c] = __bfloat16_as_ushort(__float2bfloat16(v - __bfloat162float(h)));
    }
    {
        const ush* A1h = dAh + ((long)t << 13);
        const ush* A2h = dAh + ((long)(NT + t) << 13);
        const ush* A1l = dAl + ((long)t << 13);
        const ush* A2l = dAl + ((long)(NT + t) << 13);
        for (int idx = tid; idx < 8192; idx += 256) {
            int o = idx >> 6, k = idx & 63;
            sAH[o*72 + k]        = A1h[idx];
            sAH[9216 + o*72 + k] = A2h[idx];
            sAL[o*72 + k]        = A1l[idx];
            sAL[9216 + o*72 + k] = A2l[idx];
        }
    }
    if (tid < 64) sbv[tid] = bv[tid];

    uint32_t aRow = (uint32_t)(lane & 15);
    uint32_t aKof = (uint32_t)((lane >> 4) << 3);
    uint32_t g = (uint32_t)(lane >> 3), rr8 = (uint32_t)(lane & 7);
    uint32_t tKrow = ((g & 1u) << 3) + rr8;
    uint32_t tNcol = (g >> 1) << 3;
    int grp = lane >> 2, tix = lane & 3;

    int c0 = tid >> 1, h2 = tid & 1;
    const float* x1base = x1 + base0 + (long)c0*HW;
    const float* x2base = x2 + base0 + (long)c0*HW;
    uint32_t xwo = (uint32_t)c0*72u + (uint32_t)h2*32u;

    int vm0 = (wid & 3)*16, vn0 = (wid >> 2)*32;
    int st = wid >> 2, om0 = (wid & 3)*32;
    uint32_t uA_H = uAH + (uint32_t)st*9216u*2u;
    uint32_t uA_L = uAL + (uint32_t)st*9216u*2u;
    float* outp = st ? out2 : out1;

    float4 pref[8];
    {
        const float4* src = (const float4*)(x1base + (long)(li0 + h2)*Ww);
        #pragma unroll
        for (int j = 0; j < 8; j++) pref[j] = src[j];
    }
    __syncthreads();

    for (int ch = 0; ch < 8; ch++) {
        int lrow = li0 + 2*ch;
        // step1: store X1 chunk
        #pragma unroll
        for (int j = 0; j < 8; j++) {
            float4 v = pref[j];
            __nv_bfloat16 hx = __float2bfloat16(v.x), hy = __float2bfloat16(v.y),
                          hz = __float2bfloat16(v.z), hw = __float2bfloat16(v.w);
            uint32_t off = (xwo + 4u*j)*2u;
            *(uint2*)((char*)sXH + off) = make_uint2(bfp(hx, hy), bfp(hz, hw));
            *(uint2*)((char*)sXL + off) = make_uint2(
                bfp2(v.x - __bfloat162float(hx), v.y - __bfloat162float(hy)),
                bfp2(v.z - __bfloat162float(hz), v.w - __bfloat162float(hw)));
        }
        __syncthreads();

        // step2: prefetch X2; V GEMM phase 0 (Wv cols 0..127 on X1)
        {
            const float4* src = (const float4*)(x2base + (long)(lrow + h2)*Ww);
            #pragma unroll
            for (int j = 0; j < 8; j++) pref[j] = src[j];
        }
        float accV[4][4];
        #pragma unroll
        for (int nt = 0; nt < 4; nt++)
            #pragma unroll
            for (int e = 0; e < 4; e++) accV[nt][e] = 0.f;

        #pragma unroll 2
        for (int ks = 0; ks < 8; ks++) {
            uint32_t kx = (uint32_t)(ks*16);
            uint32_t ah[4], al[4], bh[8], bl[8];
            uint32_t ao = ((uint32_t)vm0 + aRow)*264u + kx + aKof;
            ldm4(ah, uWvH + ao*2u);
            ldm4(al, uWvL + ao*2u);
            uint32_t bo0 = (kx + tKrow)*72u + (uint32_t)vn0 + tNcol;
            ldm4t(bh,     uXH + bo0*2u);
            ldm4t(bh + 4, uXH + (bo0 + 16u)*2u);
            ldm4t(bl,     uXL + bo0*2u);
            ldm4t(bl + 4, uXL + (bo0 + 16u)*2u);
            #pragma unroll
            for (int nt = 0; nt < 4; nt++) {
                mma16816(accV[nt], ah, bh + 2*nt);
                mma16816(accV[nt], ah, bl + 2*nt);
                mma16816(accV[nt], al, bh + 2*nt);
            }
        }
        __syncthreads();

        // step3: store X2 chunk
        #pragma unroll
        for (int j = 0; j < 8; j++) {
            float4 v = pref[j];
            __nv_bfloat16 hx = __float2bfloat16(v.x), hy = __float2bfloat16(v.y),
                          hz = __float2bfloat16(v.z), hw = __float2bfloat16(v.w);
            uint32_t off = (xwo + 4u*j)*2u;
            *(uint2*)((char*)sXH + off) = make_uint2(bfp(hx, hy), bfp(hz, hw));
            *(uint2*)((char*)sXL + off) = make_uint2(
                bfp2(v.x - __bfloat162float(hx), v.y - __bfloat162float(hy)),
                bfp2(v.z - __bfloat162float(hz), v.w - __bfloat162float(hw)));
        }
        __syncthreads();

        // step4: V GEMM phase 1 (Wv cols 128..255 on X2)
        #pragma unroll 2
        for (int ks = 0; ks < 8; ks++) {
            uint32_t kx = (uint32_t)(ks*16);
            uint32_t ah[4], al[4], bh[8], bl[8];
            uint32_t ao = ((uint32_t)vm0 + aRow)*264u + 128u + kx + aKof;
            ldm4(ah, uWvH + ao*2u);
            ldm4(al, uWvL + ao*2u);
            uint32_t bo0 = (kx + tKrow)*72u + (uint32_t)vn0 + tNcol;
            ldm4t(bh,     uXH + bo0*2u);
            ldm4t(bh + 4, uXH + (bo0 + 16u)*2u);
            ldm4t(bl,     uXL + bo0*2u);
            ldm4t(bl + 4, uXL + (bo0 + 16u)*2u);
            #pragma unroll
            for (int nt = 0; nt < 4; nt++) {
                mma16816(accV[nt], ah, bh + 2*nt);
                mma16816(accV[nt], ah, bl + 2*nt);
                mma16816(accV[nt], al, bh + 2*nt);
            }
        }
        // store V_raw + bias
        {
            float bv0 = sbv[vm0 + grp], bv1 = sbv[vm0 + grp + 8];
            #pragma unroll
            for (int nt = 0; nt < 4; nt++) {
                int col = vn0 + nt*8 + tix*2;
                float2 v0; v0.x = accV[nt][0] + bv0; v0.y = accV[nt][1] + bv0;
                float2 v1; v1.x = accV[nt][2] + bv1; v1.y = accV[nt][3] + bv1;
                *(float2*)(sVraw + (vm0 + grp)*72 + col)     = v0;
                *(float2*)(sVraw + (vm0 + grp + 8)*72 + col) = v1;
            }
        }
        __syncthreads();

        // step5: softmax over k per column; emit V hi/lo bf16
        {
            int col = wid*8 + (lane >> 2);
            int kg = lane & 3;
            float vals[16];
            float m = -1e30f;
            #pragma unroll
            for (int i = 0; i < 16; i++) {
                vals[i] = sVraw[(i*4 + kg)*72 + col];
                m = fmaxf(m, vals[i]);
            }
            m = fmaxf(m, __shfl_xor_sync(0xffffffffu, m, 1));
            m = fmaxf(m, __shfl_xor_sync(0xffffffffu, m, 2));
            float ssum = 0.f;
            #pragma unroll
            for (int i = 0; i < 16; i++) { float e = __expf(vals[i] - m); vals[i] = e; ssum += e; }
            ssum += __shfl_xor_sync(0xffffffffu, ssum, 1);
            ssum += __shfl_xor_sync(0xffffffffu, ssum, 2);
            float inv = 1.f / ssum;
            #pragma unroll
            for (int i = 0; i < 16; i++) {
                float v = vals[i]*inv;
                __nv_bfloat16 h = __float2bfloat16(v);
                int idx = (i*4 + kg)*72 + col;
                sVH[idx] = __bfloat16_as_ushort(h);
                sVL[idx] = __bfloat16_as_ushort(__float2bfloat16(v - __bfloat162float(h)));
            }
        }
        __syncthreads();

        // step6: out GEMM + epilogue; prefetch next X1
        {
            float accO[2][8][4];
            #pragma unroll
            for (int a = 0; a < 2; a++)
                #pragma unroll
                for (int nt = 0; nt < 8; nt++)
                    #pragma unroll
                    for (int e = 0; e < 4; e++) accO[a][nt][e] = 0.f;

            #pragma unroll
            for (int ks = 0; ks < 4; ks++) {
                uint32_t k0 = (uint32_t)(ks*16);
                uint32_t ah[2][4], al[2][4], bh[16], bl[16];
                #pragma unroll
                for (int a = 0; a < 2; a++) {
                    uint32_t ao = ((uint32_t)(om0 + a*16) + aRow)*72u + k0 + aKof;
                    ldm4(ah[a], uA_H + ao*2u);
                    ldm4(al[a], uA_L + ao*2u);
                }
                #pragma unroll
                for (int qq = 0; qq < 4; qq++) {
                    uint32_t bo = (k0 + tKrow)*72u + (uint32_t)(qq*16) + tNcol;
                    ldm4t(bh + 4*qq, uVH + bo*2u);
                    ldm4t(bl + 4*qq, uVL + bo*2u);
                }
                #pragma unroll
                for (int a = 0; a < 2; a++)
                    #pragma unroll
                    for (int nt = 0; nt < 8; nt++) {
                        const uint32_t* ph = bh + 4*(nt >> 1) + 2*(nt & 1);
                        const uint32_t* pl = bl + 4*(nt >> 1) + 2*(nt & 1);
                        mma16816(accO[a][nt], ah[a], ph);
                        mma16816(accO[a][nt], ah[a], pl);
                        mma16816(accO[a][nt], al[a], ph);
                    }
            }

            if (ch < 7) {
                const float4* src = (const float4*)(x1base + (long)(lrow + 2 + h2)*Ww);
                #pragma unroll
                for (int j = 0; j < 8; j++) pref[j] = src[j];
            }

            #pragma unroll
            for (int a = 0; a < 2; a++)
                #pragma unroll
                for (int nt = 0; nt < 8; nt++) {
                    int o = om0 + a*16 + grp;
                    int l = nt*8 + tix*2;
                    int lr = l >> 5, lj = l & 31;
                    long gaddr = ((long)(b*Cc + o)*Hh + (pi*32 + lrow + lr))*Ww + pj*32 + lj;
                    float2 v0; v0.x = accO[a][nt][0]; v0.y = accO[a][nt][1];
                    float2 v1; v1.x = accO[a][nt][2]; v1.y = accO[a][nt][3];
                    *(float2*)(outp + gaddr)              = v0;
                    *(float2*)(outp + gaddr + 8l*HW)      = v1;
                }
        }
        __syncthreads();
    }
}

extern "C" void kernel_launch(void* const* d_in, const int* in_sizes, int n_in,
                              void* d_out, int out_size)
{
    const float* x1     = (const float*)d_in[0];
    const float* x2     = (const float*)d_in[1];
    const float* w_v    = (const float*)d_in[2];
    const float* b_v    = (const float*)d_in[3];
    const float* w1_1   = (const float*)d_in[4];
    const float* b1_1   = (const float*)d_in[5];
    const float* w2_1   = (const float*)d_in[6];
    const float* b2_1   = (const float*)d_in[7];
    const float* w_out1 = (const float*)d_in[8];
    const float* w1_2   = (const float*)d_in[9];
    const float* b1_2   = (const float*)d_in[10];
    const float* w2_2   = (const float*)d_in[11];
    const float* b2_2   = (const float*)d_in[12];
    const float* w_out2 = (const float*)d_in[13];
    (void)in_sizes; (void)n_in; (void)out_size;

    float* out1 = (float*)d_out;
    float* out2 = out1 + (size_t)Bb*Cc*HW;

    cudaFuncSetAttribute(gram_kernel, cudaFuncAttributeMaxDynamicSharedMemorySize, GRAM2_SMEM);
    cudaFuncSetAttribute(mid_kernel, cudaFuncAttributeMaxDynamicSharedMemorySize, MID_SMEM);
    cudaFuncSetAttribute(out_kernel, cudaFuncAttributeMaxDynamicSharedMemorySize, OUT2_SMEM);

    gram_kernel<<<dim3(NT, 2), 256, GRAM2_SMEM>>>(x1, x2);
    mid_kernel<<<dim3(NT, 2), 256, MID_SMEM>>>(w1_1, b1_1, w2_1, b2_1, w_out1,
                                               w1_2, b1_2, w2_2, b2_2, w_out2);
    out_kernel<<<dim3(NT, 2), 256, OUT2_SMEM>>>(x1, x2, w_v, b_v, out1, out2);
}